// round 15
// baseline (speedup 1.0000x reference)
#include <cuda_runtime.h>
#include <cuda_bf16.h>
#include <cuda_fp8.h>
#include <math.h>
#include <stdint.h>

constexpr int kN   = 8192;   // points
constexpr int kD   = 256;    // dim
constexpr int kNS  = 5;      // scales
constexpr int kBM  = 128;    // block tile (M and N)
constexpr int kCK  = 32;     // fp8 K elems per chunk (one m16n8k32 step)
constexpr int kLdb = 48;     // smem row stride in bytes (32 + 16 pad)
constexpr int kStages = 3;
constexpr int kTileBytes = kBM * kLdb;     // 6144 per matrix per stage
constexpr int kChunks = kD / kCK;          // 8

// ---------------- device scratch (no allocations allowed) ----------------
__device__ double g_sumsq;
__device__ double g_colsum[kD];
__device__ unsigned int g_minbits;
__device__ unsigned int g_maxbits;
__device__ float  g_rowsq[kN];
__device__ unsigned char g_x8[kN * kD];    // fp8 e4m3 copy of x (2MB)
__device__ int    g_scales[kNS];
__device__ float  g_s2[kNS];
__device__ float  g_boxthr[kNS];
__device__ float  g_hmin;
__device__ float  g_hrange;
__device__ unsigned long long g_box_cnt[kNS];
__device__ unsigned long long g_corr_cnt[kNS];
__device__ unsigned long long g_hist[kNS][16];

__device__ __forceinline__ unsigned f2mono(float f) {
    unsigned u = __float_as_uint(f);
    return (u & 0x80000000u) ? ~u : (u | 0x80000000u);
}
__device__ __forceinline__ float mono2f(unsigned u) {
    unsigned b = (u & 0x80000000u) ? (u & 0x7fffffffu) : ~u;
    return __uint_as_float(b);
}

// ---------------- K0: zero scratch (graph replays => must re-init) ----------------
__global__ void k_init() {
    int t = threadIdx.x;
    if (t == 0) {
        g_sumsq = 0.0;
        g_minbits = 0xFFFFFFFFu;
        g_maxbits = 0u;
    }
    if (t < kD) {
        g_colsum[t] = 0.0;
    }
    if (t < kNS) {
        g_box_cnt[t] = 0ull;
        g_corr_cnt[t] = 0ull;
    }
    if (t < kNS * 16) {
        ((unsigned long long*)g_hist)[t] = 0ull;
    }
}

// ---------------- K1: fused stats + fp8 conversion + quantized row norms ----------------
__global__ void k_statscvt(const float* __restrict__ x) {
    __shared__ double s2col[8][kD];
    __shared__ double ssq[256];
    __shared__ unsigned smin[256];
    __shared__ unsigned smax[256];
    int t = threadIdx.x;
    int w = t >> 5;
    int lane = t & 31;

    double colacc[8];
    for (int i = 0; i < 8; i++) {
        colacc[i] = 0.0;
    }
    double lq = 0.0;
    unsigned lmin = 0xFFFFFFFFu;
    unsigned lmax = 0u;

    for (int it = 0; it < 8; it++) {
        int row = blockIdx.x * 64 + it * 8 + w;
        const float4* xr = (const float4*)(x + row * kD);
        float4 a = xr[lane];
        float4 b = xr[lane + 32];

        // quantize to fp8 e4m3, store, and compute rowsq from the QUANTIZED values
        __nv_fp8x4_e4m3 qa(a);
        __nv_fp8x4_e4m3 qb(b);
        uint32_t* dst8 = (uint32_t*)(g_x8 + row * kD);
        dst8[lane] = (uint32_t)qa.__x;
        dst8[lane + 32] = (uint32_t)qb.__x;

        float q0 = (float)__nv_fp8_e4m3(a.x);
        float q1 = (float)__nv_fp8_e4m3(a.y);
        float q2 = (float)__nv_fp8_e4m3(a.z);
        float q3 = (float)__nv_fp8_e4m3(a.w);
        float q4 = (float)__nv_fp8_e4m3(b.x);
        float q5 = (float)__nv_fp8_e4m3(b.y);
        float q6 = (float)__nv_fp8_e4m3(b.z);
        float q7 = (float)__nv_fp8_e4m3(b.w);
        float s = q0 * q0 + q1 * q1 + q2 * q2 + q3 * q3
                + q4 * q4 + q5 * q5 + q6 * q6 + q7 * q7;
        for (int o = 16; o > 0; o >>= 1) {
            s += __shfl_down_sync(0xffffffffu, s, o);
        }
        if (lane == 0) {
            g_rowsq[row] = s;
        }

        colacc[0] += a.x; colacc[1] += a.y; colacc[2] += a.z; colacc[3] += a.w;
        colacc[4] += b.x; colacc[5] += b.y; colacc[6] += b.z; colacc[7] += b.w;

        lq += (double)a.x * a.x + (double)a.y * a.y + (double)a.z * a.z + (double)a.w * a.w
            + (double)b.x * b.x + (double)b.y * b.y + (double)b.z * b.z + (double)b.w * b.w;
        unsigned m1 = min(min(f2mono(a.x), f2mono(a.y)), min(f2mono(a.z), f2mono(a.w)));
        unsigned m2 = min(min(f2mono(b.x), f2mono(b.y)), min(f2mono(b.z), f2mono(b.w)));
        lmin = min(lmin, min(m1, m2));
        unsigned x1 = max(max(f2mono(a.x), f2mono(a.y)), max(f2mono(a.z), f2mono(a.w)));
        unsigned x2 = max(max(f2mono(b.x), f2mono(b.y)), max(f2mono(b.z), f2mono(b.w)));
        lmax = max(lmax, max(x1, x2));
    }

    for (int j = 0; j < 4; j++) {
        s2col[w][lane * 4 + j] = colacc[j];
        s2col[w][128 + lane * 4 + j] = colacc[4 + j];
    }
    ssq[t] = lq;
    smin[t] = lmin;
    smax[t] = lmax;
    __syncthreads();

    double csum = s2col[0][t] + s2col[1][t] + s2col[2][t] + s2col[3][t]
                + s2col[4][t] + s2col[5][t] + s2col[6][t] + s2col[7][t];
    atomicAdd(&g_colsum[t], csum);

    for (int o = 128; o > 0; o >>= 1) {
        if (t < o) {
            ssq[t] += ssq[t + o];
            smin[t] = min(smin[t], smin[t + o]);
            smax[t] = max(smax[t], smax[t + o]);
        }
        __syncthreads();
    }
    if (t == 0) {
        atomicAdd(&g_sumsq, ssq[0]);
        atomicMin(&g_minbits, smin[0]);
        atomicMax(&g_maxbits, smax[0]);
    }
}

// ---------------- K2: scales + thresholds (single warp) ----------------
__global__ void k_setup(const float* __restrict__ scale_params) {
    int lane = threadIdx.x;

    double p = g_colsum[lane] + g_colsum[lane + 32] + g_colsum[lane + 64] + g_colsum[lane + 96]
             + g_colsum[lane + 128] + g_colsum[lane + 160] + g_colsum[lane + 192] + g_colsum[lane + 224];
    for (int o = 16; o > 0; o >>= 1) {
        p += __shfl_down_sync(0xffffffffu, p, o);
    }
    double tot = __shfl_sync(0xffffffffu, p, 0);

    int scl = 0;
    if (lane < kNS) {
        double nd = (double)kN * (double)kD;
        double mean = tot / nd;
        double var = (g_sumsq - nd * mean * mean) / (nd - 1.0);
        double sf = sqrt(var) / mean;
        sf = fmin(fmax(sf, 0.5), 2.0);
        double v = exp((double)scale_params[lane]) * sf;
        v = fmin(fmax(v, 2.0), 16.0);
        scl = (int)v;
        g_scales[lane] = scl;
        g_s2[lane] = (float)(scl * scl);
    }
    if (lane == 0) {
        float mn = mono2f(g_minbits);
        float mx = mono2f(g_maxbits);
        g_hmin = mn;
        g_hrange = mx - mn;
    }

    for (int i = 0; i < kNS; i++) {
        int s = __shfl_sync(0xffffffffu, scl, i);
        int n = (kD / s) * s;
        double q = 0.0;
        for (int j = lane; j < n; j += 32) {
            q += g_colsum[j];
        }
        for (int o = 16; o > 0; o >>= 1) {
            q += __shfl_down_sync(0xffffffffu, q, o);
        }
        if (lane == 0) {
            g_boxthr[i] = (float)(q / ((double)kN * (double)n));
        }
    }
}

// ---------------- K3: fused box counting + histograms (packed-key match) ----------------
__global__ void k_boxhist(const float* __restrict__ x) {
    __shared__ float pf[8][kD + 8];
    __shared__ int sh[kNS][16];
    __shared__ int sbox[kNS];
    __shared__ float sthr[kNS];
    __shared__ int sscl[kNS];
    int t = threadIdx.x;
    int w = t >> 5;
    int lane = t & 31;
    int row = blockIdx.x * 8 + w;

    if (t < kNS * 16) {
        ((int*)sh)[t] = 0;
    }
    if (t < kNS) {
        sbox[t] = 0;
        sthr[t] = g_boxthr[t];
        sscl[t] = g_scales[t];
    }

    const float4* xr = (const float4*)(x + row * kD);
    float4 va = xr[lane * 2];
    float4 vb = xr[lane * 2 + 1];
    float v[8];
    v[0] = va.x; v[1] = va.y; v[2] = va.z; v[3] = va.w;
    v[4] = vb.x; v[5] = vb.y; v[6] = vb.z; v[7] = vb.w;

    {
        float run = 0.f;
        float incl[8];
        for (int i = 0; i < 8; i++) {
            run += v[i];
            incl[i] = run;
        }
        float tsum = run;
        for (int o = 1; o < 32; o <<= 1) {
            float y = __shfl_up_sync(0xffffffffu, tsum, o);
            if (lane >= o) {
                tsum += y;
            }
        }
        float basep = tsum - run;
        for (int i = 0; i < 8; i++) {
            pf[w][lane * 8 + i + 1] = basep + incl[i];
        }
        if (lane == 0) {
            pf[w][0] = 0.f;
        }
    }
    __syncthreads();

    for (int si = 0; si < kNS; si++) {
        int s = sscl[si];
        if (si > 0 && s == sscl[si - 1]) {
            continue;
        }
        float thr = sthr[si];
        int m = kD / s;
        float inv = 1.0f / (float)s;
        int cnt = 0;
        for (int g = lane; g < m; g += 32) {
            float sum = pf[w][g * s + s] - pf[w][g * s];
            cnt += (sum * inv > thr) ? 1 : 0;
        }
        cnt = __reduce_add_sync(0xffffffffu, cnt);
        if (lane == 0) {
            atomicAdd(&sbox[si], cnt);
        }
    }

    float mn = g_hmin;
    float rng = g_hrange;
    float invr = (rng > 0.f) ? (1.0f / rng) : 0.f;
    float fs[kNS];
    int scl[kNS];
    for (int si = 0; si < kNS; si++) {
        scl[si] = sscl[si];
        fs[si] = (float)scl[si];
    }
    for (int i = 0; i < 8; i++) {
        float u = (v[i] - mn) * invr;
        int b[kNS];
        unsigned key = 0;
#pragma unroll
        for (int si = 0; si < kNS; si++) {
            int bb = (int)(u * fs[si]);
            bb = min(bb, scl[si] - 1);
            bb = max(bb, 0);
            b[si] = bb;
            key |= (unsigned)bb << (si * 4);
        }
        unsigned msk = __match_any_sync(0xffffffffu, key);
        if (lane == (__ffs(msk) - 1)) {
            int pc = __popc(msk);
#pragma unroll
            for (int si = 0; si < kNS; si++) {
                atomicAdd(&sh[si][b[si]], pc);
            }
        }
    }
    __syncthreads();
    if (t < kNS) {
        int c = t;
        while (c > 0 && sscl[c] == sscl[c - 1]) {
            c--;
        }
        atomicAdd(&g_box_cnt[t], (unsigned long long)sbox[c]);
    }
    if (t < kNS * 16) {
        int vv = ((int*)sh)[t];
        if (vv != 0) {
            atomicAdd(&((unsigned long long*)g_hist)[t], (unsigned long long)vv);
        }
    }
}

// ---------------- K5: pairwise distance counts via fp8 e4m3 tensor cores ----------------
__device__ __forceinline__ void ldmat_x4(uint32_t& r0, uint32_t& r1,
                                         uint32_t& r2, uint32_t& r3,
                                         const void* p) {
    uint32_t addr = (uint32_t)__cvta_generic_to_shared(p);
    asm volatile(
        "ldmatrix.sync.aligned.m8n8.x4.shared.b16 {%0,%1,%2,%3}, [%4];"
        : "=r"(r0), "=r"(r1), "=r"(r2), "=r"(r3)
        : "r"(addr));
}

__device__ __forceinline__ void mma_fp8(float* c, const uint32_t* a,
                                        uint32_t b0, uint32_t b1) {
    asm volatile(
        "mma.sync.aligned.m16n8k32.row.col.f32.e4m3.e4m3.f32 "
        "{%0,%1,%2,%3}, {%4,%5,%6,%7}, {%8,%9}, {%0,%1,%2,%3};"
        : "+f"(c[0]), "+f"(c[1]), "+f"(c[2]), "+f"(c[3])
        : "r"(a[0]), "r"(a[1]), "r"(a[2]), "r"(a[3]), "r"(b0), "r"(b1));
}

__device__ __forceinline__ void cp16(void* sp, const void* gp) {
    uint32_t a = (uint32_t)__cvta_generic_to_shared(sp);
    asm volatile("cp.async.ca.shared.global [%0], [%1], 16;" :: "r"(a), "l"(gp));
}
__device__ __forceinline__ void cp_commit() {
    asm volatile("cp.async.commit_group;");
}
template <int n>
__device__ __forceinline__ void cp_wait() {
    asm volatile("cp.async.wait_group %0;" :: "n"(n));
}

__global__ void __launch_bounds__(256, 2) k_corr() {
    __shared__ __align__(16) unsigned char As[kStages][kTileBytes];
    __shared__ __align__(16) unsigned char Bs[kStages][kTileBytes];

    int kblk = blockIdx.x;
    int r = (int)((sqrtf(8.0f * (float)kblk + 1.0f) - 1.0f) * 0.5f);
    while ((r + 1) * (r + 2) / 2 <= kblk) {
        r++;
    }
    while (r * (r + 1) / 2 > kblk) {
        r--;
    }
    int c = kblk - r * (r + 1) / 2;
    int bx = r;
    int by = c;
    int mult = (bx == by) ? 1 : 2;

    const unsigned char* Arows = g_x8 + by * kBM * kD;
    const unsigned char* Brows = g_x8 + bx * kBM * kD;

    int tid = threadIdx.x;
    int lane = tid & 31;
    int wid = tid >> 5;
    int warpM = wid & 3;
    int warpN = wid >> 2;
    int m0 = warpM * 32;
    int n0 = warpN * 64;

    // staging: 2 threads per row, each covers one 16B half of the 32B chunk row
    int srow = tid >> 1;
    int half = tid & 1;
    const unsigned char* ga = Arows + srow * kD + half * 16;
    const unsigned char* gb = Brows + srow * kD + half * 16;
    int soff = srow * kLdb + half * 16;

    float acc[2][8][4];
    for (int i = 0; i < 2; i++) {
        for (int j = 0; j < 8; j++) {
            for (int q = 0; q < 4; q++) {
                acc[i][j][q] = 0.f;
            }
        }
    }

    for (int ps = 0; ps < 2; ps++) {
        int kk = ps * kCK;
        cp16(&As[ps][soff], ga + kk);
        cp16(&Bs[ps][soff], gb + kk);
        cp_commit();
    }

    for (int ck = 0; ck < kChunks; ck++) {
        if (ck < kChunks - 1) {
            cp_wait<1>();
        } else {
            cp_wait<0>();
        }
        __syncthreads();
        if (ck + 2 < kChunks) {
            int nb = (ck + 2) % kStages;
            int kk = (ck + 2) * kCK;
            cp16(&As[nb][soff], ga + kk);
            cp16(&Bs[nb][soff], gb + kk);
            cp_commit();
        }
        int cb = ck % kStages;
        const unsigned char* Ab = As[cb];
        const unsigned char* Bb = Bs[cb];
        {
            uint32_t afr[2][4];
            for (int mi = 0; mi < 2; mi++) {
                const unsigned char* pa =
                    Ab + (m0 + mi * 16 + (lane & 15)) * kLdb + ((lane >> 4) & 1) * 16;
                ldmat_x4(afr[mi][0], afr[mi][1], afr[mi][2], afr[mi][3], pa);
            }
            uint32_t bfr[4][4];
            int quad = lane >> 3;
            int l7 = lane & 7;
            for (int g = 0; g < 4; g++) {
                const unsigned char* pb =
                    Bb + (n0 + g * 16 + ((quad >> 1) & 1) * 8 + l7) * kLdb + (quad & 1) * 16;
                ldmat_x4(bfr[g][0], bfr[g][1], bfr[g][2], bfr[g][3], pb);
            }
            for (int mi = 0; mi < 2; mi++) {
                for (int nt = 0; nt < 8; nt++) {
                    int g = nt >> 1;
                    int ph = nt & 1;
                    mma_fp8(acc[mi][nt], afr[mi], bfr[g][ph * 2], bfr[g][ph * 2 + 1]);
                }
            }
        }
    }

    float sqa[2][2];
    for (int mi = 0; mi < 2; mi++) {
        for (int h = 0; h < 2; h++) {
            sqa[mi][h] = g_rowsq[by * kBM + m0 + mi * 16 + (lane >> 2) + h * 8];
        }
    }
    float sqb[8][2];
    for (int nt = 0; nt < 8; nt++) {
        for (int j = 0; j < 2; j++) {
            sqb[nt][j] = g_rowsq[bx * kBM + n0 + nt * 8 + 2 * (lane & 3) + j];
        }
    }

    float s2[kNS];
    for (int q = 0; q < kNS; q++) {
        s2[q] = g_s2[q];
    }
    int cnt[kNS];
    for (int q = 0; q < kNS; q++) {
        cnt[q] = 0;
    }
    for (int mi = 0; mi < 2; mi++) {
        for (int nt = 0; nt < 8; nt++) {
            for (int q4 = 0; q4 < 4; q4++) {
                int h = q4 >> 1;
                int j = q4 & 1;
                float d2 = sqa[mi][h] + sqb[nt][j] - 2.0f * acc[mi][nt][q4];
                for (int q = 0; q < kNS; q++) {
                    cnt[q] += (d2 < s2[q]) ? 1 : 0;
                }
            }
        }
    }

    __shared__ int scnt[kNS];
    if (tid < kNS) {
        scnt[tid] = 0;
    }
    __syncthreads();
    for (int q = 0; q < kNS; q++) {
        int vv = __reduce_add_sync(0xffffffffu, cnt[q]);
        if (lane == 0) {
            atomicAdd(&scnt[q], vv);
        }
    }
    __syncthreads();
    if (tid < kNS) {
        long long total = (long long)scnt[tid] * (long long)mult;
        atomicAdd(&g_corr_cnt[tid], (unsigned long long)total);
    }
}

// ---------------- K6: slopes + softmax-weighted output (one warp) ----------------
__global__ void k_final(const float* __restrict__ simp, float* __restrict__ outp) {
    int lane = threadIdx.x;
    bool act = lane < kNS;

    double lg = 0.0, yb = 0.0, yc = 0.0, yi = 0.0;
    if (act) {
        int scl = g_scales[lane];
        lg = log((double)(float)scl);
        yb = log((double)g_box_cnt[lane]);
        yc = log((double)g_corr_cnt[lane]);
        unsigned long long tot = 0;
        for (int b = 0; b < scl; b++) {
            tot += g_hist[lane][b];
        }
        double ent = 0.0;
        for (int b = 0; b < scl; b++) {
            if (g_hist[lane][b] > 0) {
                double p = (double)g_hist[lane][b] / (double)tot;
                ent -= p * log(p);
            }
        }
        yi = ent;
    }

    double sx = lg, sxx = lg * lg;
    double sb = yb, sbx = lg * yb;
    double sc = yc, scx = lg * yc;
    double si = yi, six = lg * yi;
    for (int o = 16; o > 0; o >>= 1) {
        sx  += __shfl_down_sync(0xffffffffu, sx,  o);
        sxx += __shfl_down_sync(0xffffffffu, sxx, o);
        sb  += __shfl_down_sync(0xffffffffu, sb,  o);
        sbx += __shfl_down_sync(0xffffffffu, sbx, o);
        sc  += __shfl_down_sync(0xffffffffu, sc,  o);
        scx += __shfl_down_sync(0xffffffffu, scx, o);
        si  += __shfl_down_sync(0xffffffffu, si,  o);
        six += __shfl_down_sync(0xffffffffu, six, o);
    }

    float sv = act ? simp[lane] : -3.0e38f;
    float mx = sv;
    for (int o = 16; o > 0; o >>= 1) {
        mx = fmaxf(mx, __shfl_down_sync(0xffffffffu, mx, o));
    }
    mx = __shfl_sync(0xffffffffu, mx, 0);
    double wv = act ? exp((double)(sv - mx)) : 0.0;
    double wsum = wv;
    for (int o = 16; o > 0; o >>= 1) {
        wsum += __shfl_down_sync(0xffffffffu, wsum, o);
    }
    double w0 = __shfl_sync(0xffffffffu, wv, 0);
    double w1 = __shfl_sync(0xffffffffu, wv, 1);
    double w2 = __shfl_sync(0xffffffffu, wv, 2);

    if (lane == 0) {
        double n = (double)kNS;
        double den = sxx - sx * sx / n;
        double box_dim  = -((sbx - sx * sb / n) / den);
        double corr_dim =  ((scx - sx * sc / n) / den);
        double info_dim =  ((six - sx * si / n) / den);
        double o = (w0 * box_dim + w1 * corr_dim + w2 * info_dim) / wsum;
        outp[0] = (float)o;
    }
}

// ---------------- launch ----------------
extern "C" void kernel_launch(void* const* d_in, const int* in_sizes, int n_in,
                              void* d_out, int out_size) {
    const float* x = (const float*)d_in[0];
    const float* sp = (const float*)d_in[1];
    const float* simp = (const float*)d_in[2];
    float* outp = (float*)d_out;

    k_init<<<1, 256>>>();
    k_statscvt<<<128, 256>>>(x);
    k_setup<<<1, 32>>>(sp);
    k_boxhist<<<kN / 8, 256>>>(x);
    int ntiles = kN / kBM;
    k_corr<<<ntiles * (ntiles + 1) / 2, 256>>>();
    k_final<<<1, 32>>>(simp, outp);
}

// round 16
// speedup vs baseline: 1.0279x; 1.0279x over previous
#include <cuda_runtime.h>
#include <cuda_bf16.h>
#include <cuda_fp8.h>
#include <math.h>
#include <stdint.h>

constexpr int kN   = 8192;   // points
constexpr int kD   = 256;    // dim
constexpr int kNS  = 5;      // scales
constexpr int kBM  = 128;    // block tile (M and N)
constexpr int kCK  = 32;     // fp8 K elems per chunk (one m16n8k32 step)
constexpr int kLdb = 48;     // smem row stride in bytes (32 + 16 pad)
constexpr int kStages = 3;
constexpr int kTileBytes = kBM * kLdb;     // 6144 per matrix per stage
constexpr int kChunks = kD / kCK;          // 8

// ---------------- device scratch (no allocations allowed) ----------------
__device__ double g_sumsq;
__device__ double g_colsum[kD];
__device__ unsigned int g_minbits;
__device__ unsigned int g_maxbits;
__device__ float  g_rowsq[kN];
__device__ unsigned char g_x8[kN * kD];    // fp8 e4m3 copy of x (2MB)
__device__ int    g_scales[kNS];
__device__ float  g_s2[kNS];
__device__ float  g_boxthr[kNS];
__device__ float  g_hmin;
__device__ float  g_hrange;
__device__ unsigned long long g_box_cnt[kNS];
__device__ unsigned long long g_corr_cnt[kNS];
__device__ unsigned long long g_hist[kNS][16];

__device__ __forceinline__ unsigned f2mono(float f) {
    unsigned u = __float_as_uint(f);
    return (u & 0x80000000u) ? ~u : (u | 0x80000000u);
}
__device__ __forceinline__ float mono2f(unsigned u) {
    unsigned b = (u & 0x80000000u) ? (u & 0x7fffffffu) : ~u;
    return __uint_as_float(b);
}

// ---------------- K0: zero scratch (graph replays => must re-init) ----------------
__global__ void k_init() {
    int t = threadIdx.x;
    if (t == 0) {
        g_sumsq = 0.0;
        g_minbits = 0xFFFFFFFFu;
        g_maxbits = 0u;
    }
    if (t < kD) {
        g_colsum[t] = 0.0;
    }
    if (t < kNS) {
        g_box_cnt[t] = 0ull;
        g_corr_cnt[t] = 0ull;
    }
    if (t < kNS * 16) {
        ((unsigned long long*)g_hist)[t] = 0ull;
    }
}

// ---------------- K1: fused stats + fp8 conversion + quantized row norms ----------------
__global__ void k_statscvt(const float* __restrict__ x) {
    __shared__ double s2col[8][kD];
    __shared__ double ssq[256];
    __shared__ unsigned smin[256];
    __shared__ unsigned smax[256];
    int t = threadIdx.x;
    int w = t >> 5;
    int lane = t & 31;

    double colacc[8];
    for (int i = 0; i < 8; i++) {
        colacc[i] = 0.0;
    }
    double lq = 0.0;
    unsigned lmin = 0xFFFFFFFFu;
    unsigned lmax = 0u;

    for (int it = 0; it < 8; it++) {
        int row = blockIdx.x * 64 + it * 8 + w;
        const float4* xr = (const float4*)(x + row * kD);
        float4 a = xr[lane];
        float4 b = xr[lane + 32];

        // quantize to fp8 e4m3, store, and compute rowsq from the QUANTIZED values
        __nv_fp8x4_e4m3 qa(a);
        __nv_fp8x4_e4m3 qb(b);
        uint32_t* dst8 = (uint32_t*)(g_x8 + row * kD);
        dst8[lane] = (uint32_t)qa.__x;
        dst8[lane + 32] = (uint32_t)qb.__x;

        float q0 = (float)__nv_fp8_e4m3(a.x);
        float q1 = (float)__nv_fp8_e4m3(a.y);
        float q2 = (float)__nv_fp8_e4m3(a.z);
        float q3 = (float)__nv_fp8_e4m3(a.w);
        float q4 = (float)__nv_fp8_e4m3(b.x);
        float q5 = (float)__nv_fp8_e4m3(b.y);
        float q6 = (float)__nv_fp8_e4m3(b.z);
        float q7 = (float)__nv_fp8_e4m3(b.w);
        float s = q0 * q0 + q1 * q1 + q2 * q2 + q3 * q3
                + q4 * q4 + q5 * q5 + q6 * q6 + q7 * q7;
        for (int o = 16; o > 0; o >>= 1) {
            s += __shfl_down_sync(0xffffffffu, s, o);
        }
        if (lane == 0) {
            g_rowsq[row] = s;
        }

        colacc[0] += a.x; colacc[1] += a.y; colacc[2] += a.z; colacc[3] += a.w;
        colacc[4] += b.x; colacc[5] += b.y; colacc[6] += b.z; colacc[7] += b.w;

        lq += (double)a.x * a.x + (double)a.y * a.y + (double)a.z * a.z + (double)a.w * a.w
            + (double)b.x * b.x + (double)b.y * b.y + (double)b.z * b.z + (double)b.w * b.w;
        unsigned m1 = min(min(f2mono(a.x), f2mono(a.y)), min(f2mono(a.z), f2mono(a.w)));
        unsigned m2 = min(min(f2mono(b.x), f2mono(b.y)), min(f2mono(b.z), f2mono(b.w)));
        lmin = min(lmin, min(m1, m2));
        unsigned x1 = max(max(f2mono(a.x), f2mono(a.y)), max(f2mono(a.z), f2mono(a.w)));
        unsigned x2 = max(max(f2mono(b.x), f2mono(b.y)), max(f2mono(b.z), f2mono(b.w)));
        lmax = max(lmax, max(x1, x2));
    }

    for (int j = 0; j < 4; j++) {
        s2col[w][lane * 4 + j] = colacc[j];
        s2col[w][128 + lane * 4 + j] = colacc[4 + j];
    }
    ssq[t] = lq;
    smin[t] = lmin;
    smax[t] = lmax;
    __syncthreads();

    double csum = s2col[0][t] + s2col[1][t] + s2col[2][t] + s2col[3][t]
                + s2col[4][t] + s2col[5][t] + s2col[6][t] + s2col[7][t];
    atomicAdd(&g_colsum[t], csum);

    for (int o = 128; o > 0; o >>= 1) {
        if (t < o) {
            ssq[t] += ssq[t + o];
            smin[t] = min(smin[t], smin[t + o]);
            smax[t] = max(smax[t], smax[t + o]);
        }
        __syncthreads();
    }
    if (t == 0) {
        atomicAdd(&g_sumsq, ssq[0]);
        atomicMin(&g_minbits, smin[0]);
        atomicMax(&g_maxbits, smax[0]);
    }
}

// ---------------- K2: scales + thresholds (single warp) ----------------
__global__ void k_setup(const float* __restrict__ scale_params) {
    int lane = threadIdx.x;

    double p = g_colsum[lane] + g_colsum[lane + 32] + g_colsum[lane + 64] + g_colsum[lane + 96]
             + g_colsum[lane + 128] + g_colsum[lane + 160] + g_colsum[lane + 192] + g_colsum[lane + 224];
    for (int o = 16; o > 0; o >>= 1) {
        p += __shfl_down_sync(0xffffffffu, p, o);
    }
    double tot = __shfl_sync(0xffffffffu, p, 0);

    int scl = 0;
    if (lane < kNS) {
        double nd = (double)kN * (double)kD;
        double mean = tot / nd;
        double var = (g_sumsq - nd * mean * mean) / (nd - 1.0);
        double sf = sqrt(var) / mean;
        sf = fmin(fmax(sf, 0.5), 2.0);
        double v = exp((double)scale_params[lane]) * sf;
        v = fmin(fmax(v, 2.0), 16.0);
        scl = (int)v;
        g_scales[lane] = scl;
        g_s2[lane] = (float)(scl * scl);
    }
    if (lane == 0) {
        float mn = mono2f(g_minbits);
        float mx = mono2f(g_maxbits);
        g_hmin = mn;
        g_hrange = mx - mn;
    }

    for (int i = 0; i < kNS; i++) {
        int s = __shfl_sync(0xffffffffu, scl, i);
        int n = (kD / s) * s;
        double q = 0.0;
        for (int j = lane; j < n; j += 32) {
            q += g_colsum[j];
        }
        for (int o = 16; o > 0; o >>= 1) {
            q += __shfl_down_sync(0xffffffffu, q, o);
        }
        if (lane == 0) {
            g_boxthr[i] = (float)(q / ((double)kN * (double)n));
        }
    }
}

// ---------------- K3: fused box counting + histograms (packed-key match) ----------------
__global__ void k_boxhist(const float* __restrict__ x) {
    __shared__ float pf[8][kD + 8];
    __shared__ int sh[kNS][16];
    __shared__ int sbox[kNS];
    __shared__ float sthr[kNS];
    __shared__ int sscl[kNS];
    int t = threadIdx.x;
    int w = t >> 5;
    int lane = t & 31;
    int row = blockIdx.x * 8 + w;

    if (t < kNS * 16) {
        ((int*)sh)[t] = 0;
    }
    if (t < kNS) {
        sbox[t] = 0;
        sthr[t] = g_boxthr[t];
        sscl[t] = g_scales[t];
    }

    const float4* xr = (const float4*)(x + row * kD);
    float4 va = xr[lane * 2];
    float4 vb = xr[lane * 2 + 1];
    float v[8];
    v[0] = va.x; v[1] = va.y; v[2] = va.z; v[3] = va.w;
    v[4] = vb.x; v[5] = vb.y; v[6] = vb.z; v[7] = vb.w;

    {
        float run = 0.f;
        float incl[8];
        for (int i = 0; i < 8; i++) {
            run += v[i];
            incl[i] = run;
        }
        float tsum = run;
        for (int o = 1; o < 32; o <<= 1) {
            float y = __shfl_up_sync(0xffffffffu, tsum, o);
            if (lane >= o) {
                tsum += y;
            }
        }
        float basep = tsum - run;
        for (int i = 0; i < 8; i++) {
            pf[w][lane * 8 + i + 1] = basep + incl[i];
        }
        if (lane == 0) {
            pf[w][0] = 0.f;
        }
    }
    __syncthreads();

    for (int si = 0; si < kNS; si++) {
        int s = sscl[si];
        if (si > 0 && s == sscl[si - 1]) {
            continue;
        }
        float thr = sthr[si];
        int m = kD / s;
        float inv = 1.0f / (float)s;
        int cnt = 0;
        for (int g = lane; g < m; g += 32) {
            float sum = pf[w][g * s + s] - pf[w][g * s];
            cnt += (sum * inv > thr) ? 1 : 0;
        }
        cnt = __reduce_add_sync(0xffffffffu, cnt);
        if (lane == 0) {
            atomicAdd(&sbox[si], cnt);
        }
    }

    float mn = g_hmin;
    float rng = g_hrange;
    float invr = (rng > 0.f) ? (1.0f / rng) : 0.f;
    float fs[kNS];
    int scl[kNS];
    for (int si = 0; si < kNS; si++) {
        scl[si] = sscl[si];
        fs[si] = (float)scl[si];
    }
    for (int i = 0; i < 8; i++) {
        float u = (v[i] - mn) * invr;
        int b[kNS];
        unsigned key = 0;
#pragma unroll
        for (int si = 0; si < kNS; si++) {
            int bb = (int)(u * fs[si]);
            bb = min(bb, scl[si] - 1);
            bb = max(bb, 0);
            b[si] = bb;
            key |= (unsigned)bb << (si * 4);
        }
        unsigned msk = __match_any_sync(0xffffffffu, key);
        if (lane == (__ffs(msk) - 1)) {
            int pc = __popc(msk);
#pragma unroll
            for (int si = 0; si < kNS; si++) {
                atomicAdd(&sh[si][b[si]], pc);
            }
        }
    }
    __syncthreads();
    if (t < kNS) {
        int c = t;
        while (c > 0 && sscl[c] == sscl[c - 1]) {
            c--;
        }
        atomicAdd(&g_box_cnt[t], (unsigned long long)sbox[c]);
    }
    if (t < kNS * 16) {
        int vv = ((int*)sh)[t];
        if (vv != 0) {
            atomicAdd(&((unsigned long long*)g_hist)[t], (unsigned long long)vv);
        }
    }
}

// ---------------- K5: pairwise distance counts via fp8 e4m3 tensor cores ----------------
__device__ __forceinline__ void ldmat_x4(uint32_t& r0, uint32_t& r1,
                                         uint32_t& r2, uint32_t& r3,
                                         const void* p) {
    uint32_t addr = (uint32_t)__cvta_generic_to_shared(p);
    asm volatile(
        "ldmatrix.sync.aligned.m8n8.x4.shared.b16 {%0,%1,%2,%3}, [%4];"
        : "=r"(r0), "=r"(r1), "=r"(r2), "=r"(r3)
        : "r"(addr));
}

__device__ __forceinline__ void mma_fp8(float* c, const uint32_t* a,
                                        uint32_t b0, uint32_t b1) {
    asm volatile(
        "mma.sync.aligned.m16n8k32.row.col.f32.e4m3.e4m3.f32 "
        "{%0,%1,%2,%3}, {%4,%5,%6,%7}, {%8,%9}, {%0,%1,%2,%3};"
        : "+f"(c[0]), "+f"(c[1]), "+f"(c[2]), "+f"(c[3])
        : "r"(a[0]), "r"(a[1]), "r"(a[2]), "r"(a[3]), "r"(b0), "r"(b1));
}

__device__ __forceinline__ void cp16(void* sp, const void* gp) {
    uint32_t a = (uint32_t)__cvta_generic_to_shared(sp);
    asm volatile("cp.async.ca.shared.global [%0], [%1], 16;" :: "r"(a), "l"(gp));
}
__device__ __forceinline__ void cp_commit() {
    asm volatile("cp.async.commit_group;");
}
template <int n>
__device__ __forceinline__ void cp_wait() {
    asm volatile("cp.async.wait_group %0;" :: "n"(n));
}

__global__ void __launch_bounds__(256, 2) k_corr() {
    __shared__ __align__(16) unsigned char As[kStages][kTileBytes];
    __shared__ __align__(16) unsigned char Bs[kStages][kTileBytes];

    int kblk = blockIdx.x;
    int r = (int)((sqrtf(8.0f * (float)kblk + 1.0f) - 1.0f) * 0.5f);
    while ((r + 1) * (r + 2) / 2 <= kblk) {
        r++;
    }
    while (r * (r + 1) / 2 > kblk) {
        r--;
    }
    int c = kblk - r * (r + 1) / 2;
    int bx = r;
    int by = c;
    int mult = (bx == by) ? 1 : 2;

    const unsigned char* Arows = g_x8 + by * kBM * kD;
    const unsigned char* Brows = g_x8 + bx * kBM * kD;

    int tid = threadIdx.x;
    int lane = tid & 31;
    int wid = tid >> 5;
    int warpM = wid & 3;
    int warpN = wid >> 2;
    int m0 = warpM * 32;
    int n0 = warpN * 64;

    int srow = tid >> 1;
    int half = tid & 1;
    const unsigned char* ga = Arows + srow * kD + half * 16;
    const unsigned char* gb = Brows + srow * kD + half * 16;
    int soff = srow * kLdb + half * 16;

    float acc[2][8][4];
    for (int i = 0; i < 2; i++) {
        for (int j = 0; j < 8; j++) {
            for (int q = 0; q < 4; q++) {
                acc[i][j][q] = 0.f;
            }
        }
    }

    for (int ps = 0; ps < 2; ps++) {
        int kk = ps * kCK;
        cp16(&As[ps][soff], ga + kk);
        cp16(&Bs[ps][soff], gb + kk);
        cp_commit();
    }

    for (int ck = 0; ck < kChunks; ck++) {
        if (ck < kChunks - 1) {
            cp_wait<1>();
        } else {
            cp_wait<0>();
        }
        __syncthreads();
        if (ck + 2 < kChunks) {
            int nb = (ck + 2) % kStages;
            int kk = (ck + 2) * kCK;
            cp16(&As[nb][soff], ga + kk);
            cp16(&Bs[nb][soff], gb + kk);
            cp_commit();
        }
        int cb = ck % kStages;
        const unsigned char* Ab = As[cb];
        const unsigned char* Bb = Bs[cb];
        {
            uint32_t afr[2][4];
            for (int mi = 0; mi < 2; mi++) {
                const unsigned char* pa =
                    Ab + (m0 + mi * 16 + (lane & 15)) * kLdb + ((lane >> 4) & 1) * 16;
                ldmat_x4(afr[mi][0], afr[mi][1], afr[mi][2], afr[mi][3], pa);
            }
            uint32_t bfr[4][4];
            int quad = lane >> 3;
            int l7 = lane & 7;
            for (int g = 0; g < 4; g++) {
                const unsigned char* pb =
                    Bb + (n0 + g * 16 + ((quad >> 1) & 1) * 8 + l7) * kLdb + (quad & 1) * 16;
                ldmat_x4(bfr[g][0], bfr[g][1], bfr[g][2], bfr[g][3], pb);
            }
            for (int mi = 0; mi < 2; mi++) {
                for (int nt = 0; nt < 8; nt++) {
                    int g = nt >> 1;
                    int ph = nt & 1;
                    mma_fp8(acc[mi][nt], afr[mi], bfr[g][ph * 2], bfr[g][ph * 2 + 1]);
                }
            }
        }
    }

    float sqa[2][2];
    for (int mi = 0; mi < 2; mi++) {
        for (int h = 0; h < 2; h++) {
            sqa[mi][h] = g_rowsq[by * kBM + m0 + mi * 16 + (lane >> 2) + h * 8];
        }
    }
    float sqb[8][2];
    for (int nt = 0; nt < 8; nt++) {
        for (int j = 0; j < 2; j++) {
            sqb[nt][j] = g_rowsq[bx * kBM + n0 + nt * 8 + 2 * (lane & 3) + j];
        }
    }

    float s2[kNS];
    for (int q = 0; q < kNS; q++) {
        s2[q] = g_s2[q];
    }
    int cnt[kNS];
    for (int q = 0; q < kNS; q++) {
        cnt[q] = 0;
    }
    for (int mi = 0; mi < 2; mi++) {
        for (int nt = 0; nt < 8; nt++) {
            for (int q4 = 0; q4 < 4; q4++) {
                int h = q4 >> 1;
                int j = q4 & 1;
                float d2 = sqa[mi][h] + sqb[nt][j] - 2.0f * acc[mi][nt][q4];
                for (int q = 0; q < kNS; q++) {
                    cnt[q] += (d2 < s2[q]) ? 1 : 0;
                }
            }
        }
    }

    __shared__ int scnt[kNS];
    if (tid < kNS) {
        scnt[tid] = 0;
    }
    __syncthreads();
    for (int q = 0; q < kNS; q++) {
        int vv = __reduce_add_sync(0xffffffffu, cnt[q]);
        if (lane == 0) {
            atomicAdd(&scnt[q], vv);
        }
    }
    __syncthreads();
    if (tid < kNS) {
        long long total = (long long)scnt[tid] * (long long)mult;
        atomicAdd(&g_corr_cnt[tid], (unsigned long long)total);
    }
}

// ---------------- K6: slopes + softmax-weighted output (one warp) ----------------
__global__ void k_final(const float* __restrict__ simp, float* __restrict__ outp) {
    int lane = threadIdx.x;
    bool act = lane < kNS;

    double lg = 0.0, yb = 0.0, yc = 0.0, yi = 0.0;
    if (act) {
        int scl = g_scales[lane];
        lg = log((double)(float)scl);
        yb = log((double)g_box_cnt[lane]);
        yc = log((double)g_corr_cnt[lane]);
        unsigned long long tot = 0;
        for (int b = 0; b < scl; b++) {
            tot += g_hist[lane][b];
        }
        double ent = 0.0;
        for (int b = 0; b < scl; b++) {
            if (g_hist[lane][b] > 0) {
                double p = (double)g_hist[lane][b] / (double)tot;
                ent -= p * log(p);
            }
        }
        yi = ent;
    }

    double sx = lg, sxx = lg * lg;
    double sb = yb, sbx = lg * yb;
    double sc = yc, scx = lg * yc;
    double si = yi, six = lg * yi;
    for (int o = 16; o > 0; o >>= 1) {
        sx  += __shfl_down_sync(0xffffffffu, sx,  o);
        sxx += __shfl_down_sync(0xffffffffu, sxx, o);
        sb  += __shfl_down_sync(0xffffffffu, sb,  o);
        sbx += __shfl_down_sync(0xffffffffu, sbx, o);
        sc  += __shfl_down_sync(0xffffffffu, sc,  o);
        scx += __shfl_down_sync(0xffffffffu, scx, o);
        si  += __shfl_down_sync(0xffffffffu, si,  o);
        six += __shfl_down_sync(0xffffffffu, six, o);
    }

    float sv = act ? simp[lane] : -3.0e38f;
    float mx = sv;
    for (int o = 16; o > 0; o >>= 1) {
        mx = fmaxf(mx, __shfl_down_sync(0xffffffffu, mx, o));
    }
    mx = __shfl_sync(0xffffffffu, mx, 0);
    double wv = act ? exp((double)(sv - mx)) : 0.0;
    double wsum = wv;
    for (int o = 16; o > 0; o >>= 1) {
        wsum += __shfl_down_sync(0xffffffffu, wsum, o);
    }
    double w0 = __shfl_sync(0xffffffffu, wv, 0);
    double w1 = __shfl_sync(0xffffffffu, wv, 1);
    double w2 = __shfl_sync(0xffffffffu, wv, 2);

    if (lane == 0) {
        double n = (double)kNS;
        double den = sxx - sx * sx / n;
        double box_dim  = -((sbx - sx * sb / n) / den);
        double corr_dim =  ((scx - sx * sc / n) / den);
        double info_dim =  ((six - sx * si / n) / den);
        double o = (w0 * box_dim + w1 * corr_dim + w2 * info_dim) / wsum;
        outp[0] = (float)o;
    }
}

// ---------------- launch: fork boxhist onto a side stream, overlap with corr ----------------
extern "C" void kernel_launch(void* const* d_in, const int* in_sizes, int n_in,
                              void* d_out, int out_size) {
    const float* x = (const float*)d_in[0];
    const float* sp = (const float*)d_in[1];
    const float* simp = (const float*)d_in[2];
    float* outp = (float*)d_out;

    // host-side resources only (no device memory); created per call, leaked
    // (kernel_launch runs a handful of times; graph replays don't re-enter it)
    cudaStream_t s2;
    cudaStreamCreateWithFlags(&s2, cudaStreamNonBlocking);
    cudaEvent_t ev1, ev2;
    cudaEventCreateWithFlags(&ev1, cudaEventDisableTiming);
    cudaEventCreateWithFlags(&ev2, cudaEventDisableTiming);

    k_init<<<1, 256>>>();
    k_statscvt<<<128, 256>>>(x);
    k_setup<<<1, 32>>>(sp);

    // fork: boxhist runs concurrently with corr
    cudaEventRecord(ev1, 0);
    cudaStreamWaitEvent(s2, ev1, 0);
    k_boxhist<<<kN / 8, 256, 0, s2>>>(x);

    int ntiles = kN / kBM;
    k_corr<<<ntiles * (ntiles + 1) / 2, 256>>>();

    // join
    cudaEventRecord(ev2, s2);
    cudaStreamWaitEvent(0, ev2, 0);
    k_final<<<1, 32>>>(simp, outp);
}